// round 1
// baseline (speedup 1.0000x reference)
#include <cuda_runtime.h>

#define T_MAX 2048
#define L_MAX (T_MAX * 16 + 64)

__device__ float          d_w[T_MAX];
__device__ float          d_startf[T_MAX];
__device__ float          d_endf[T_MAX];
__device__ unsigned short d_owner[L_MAX];

__device__ __forceinline__ float reluf(float x) { return x > 0.f ? x : 0.f; }

__device__ __forceinline__ float rerelu_f(float x) {
    const float offs[24] = {3.25f,3.75f,5.25f,5.75f,6.25f,6.75f,11.25f,11.75f,
                            15.25f,15.75f,20.25f,20.75f,23.25f,23.75f,35.25f,35.75f,
                            40.25f,40.75f,43.25f,43.75f,49.25f,49.75f,61.25f,61.75f};
    const float cfs[24]  = {4.f,-4.f,-4.f,4.f,4.f,-4.f,-2.f,2.f,2.f,-2.f,-2.f,2.f,
                            2.f,-2.f,-2.f,2.f,2.f,-2.f,-2.f,2.f,2.f,-2.f,-2.f,2.f};
    float s = 0.f;
#pragma unroll
    for (int k = 0; k < 24; k++)
        s = __fadd_rn(s, __fmul_rn(cfs[k], reluf(__fadd_rn(x, -offs[k]))));
    return s;
}

__device__ __forceinline__ float rerelu2_f(float x) {
    const float offs[6] = {1.25f,1.75f,2.25f,2.75f,3.25f,3.75f};
    const float cfs[6]  = {-2.f,2.f,2.f,-2.f,-2.f,2.f};
    float s = 1.f;
#pragma unroll
    for (int k = 0; k < 6; k++)
        s = __fadd_rn(s, __fmul_rn(cfs[k], reluf(__fadd_rn(x, -offs[k]))));
    return s;
}

__device__ __forceinline__ float rerelu3_f(float x) {
    float s = __fmul_rn(2.f, reluf(__fadd_rn(x, -1.25f)));
    s = __fadd_rn(s, __fmul_rn(-2.f, reluf(__fadd_rn(x, -1.75f))));
    return s;
}

__device__ __forceinline__ float rerelu4_f(float x) {
    float s = __fmul_rn(8.f, reluf(x));
    s = __fadd_rn(s, __fmul_rn(-8.f,  reluf(__fadd_rn(x, -1.f))));
    s = __fadd_rn(s, __fmul_rn(-0.3f, reluf(__fadd_rn(x, -1.f))));
    s = __fadd_rn(s, __fmul_rn(0.3f,  reluf(__fadd_rn(x, -21.f))));
    return s;
}

// ---------------------------------------------------------------------------
// Kernel A: per-token prep (one CTA). Computes tok = rerelu(token), duration
// scan (start_t), end_t = start + rerelu2(tok_t+tok_{t+1})*dur_{t+1} + dur_t,
// w_t = rerelu3(tok_t)^2, and the owner[l] map for l in [start_t, start_t+dur_t).
// ---------------------------------------------------------------------------
__global__ __launch_bounds__(1024) void prep_kernel(const int* __restrict__ dur,
                                                    const float* __restrict__ token,
                                                    int T) {
    __shared__ float s_tok[T_MAX + 1];
    __shared__ int   s_wsum[32];
    int tid = threadIdx.x;

    for (int t = tid; t <= T_MAX; t += 1024)
        s_tok[t] = (t < T) ? rerelu_f(token[t]) : 0.f;

    int t0 = 2 * tid, t1 = 2 * tid + 1;
    int d0 = (t0 < T) ? dur[t0] : 0;
    int d1 = (t1 < T) ? dur[t1] : 0;
    int d2 = (t1 + 1 < T) ? dur[t1 + 1] : 0;
    int pair = d0 + d1;

    int lane = tid & 31, wid = tid >> 5;
    int incl = pair;
#pragma unroll
    for (int o = 1; o < 32; o <<= 1) {
        int n = __shfl_up_sync(0xffffffffu, incl, o);
        if (lane >= o) incl += n;
    }
    if (lane == 31) s_wsum[wid] = incl;
    __syncthreads();
    if (wid == 0) {
        int v = s_wsum[lane];
        int wincl = v;
#pragma unroll
        for (int o = 1; o < 32; o <<= 1) {
            int n = __shfl_up_sync(0xffffffffu, wincl, o);
            if (lane >= o) wincl += n;
        }
        s_wsum[lane] = wincl - v;  // exclusive warp offset
    }
    __syncthreads();
    int excl = s_wsum[wid] + incl - pair;  // exclusive prefix of dur before token t0

    int starts[2] = {excl, excl + d0};
    int ds[2] = {d0, d1};
    int dn[2] = {d1, d2};

#pragma unroll
    for (int j = 0; j < 2; j++) {
        int t = 2 * tid + j;
        if (t < T) {
            float st = s_tok[t];
            float x  = __fadd_rn(st, s_tok[t + 1]);
            float s2 = rerelu2_f(x);
            float nd = __fadd_rn(__fmul_rn(s2, (float)dn[j]), (float)ds[j]);
            float sf = (float)starts[j];
            d_startf[t] = sf;
            d_endf[t]   = __fadd_rn(sf, nd);
            float nt = rerelu3_f(st);
            d_w[t] = __fmul_rn(nt, nt);
            for (int k = 0; k < ds[j]; k++)
                d_owner[starts[j] + k] = (unsigned short)t;
        }
    }
}

// ---------------------------------------------------------------------------
// Kernel B: per output frame l, S[l] = w_t*(l-start_t+1) (+ predecessor term
// if l < end_{t-1}); mel = rerelu4(S), broadcast to 128 channels, float4 stores.
// ---------------------------------------------------------------------------
#define BL 64

__global__ __launch_bounds__(256) void fill_kernel(float* __restrict__ out, int L) {
    __shared__ float s_mel[BL];
    int l0 = blockIdx.x * BL;
    int tid = threadIdx.x;

    if (tid < BL) {
        int l = l0 + tid;
        if (l < L) {
            int t = (int)d_owner[l];
            float lf = (float)l;
            float S = __fmul_rn(d_w[t], __fadd_rn(__fadd_rn(lf, -d_startf[t]), 1.f));
            if (t > 0) {
                if (lf < d_endf[t - 1]) {
                    float c = __fmul_rn(d_w[t - 1],
                                        __fadd_rn(__fadd_rn(lf, -d_startf[t - 1]), 1.f));
                    S = __fadd_rn(S, c);
                }
            }
            s_mel[tid] = rerelu4_f(S);
        }
    }
    __syncthreads();

    float4* o4 = (float4*)out;
    long long base = (long long)l0 * 32;  // 128 floats = 32 float4 per frame
    int total = BL * 32;
#pragma unroll 4
    for (int i = tid; i < total; i += 256) {
        int ll = l0 + (i >> 5);
        if (ll < L) {
            float v = s_mel[i >> 5];
            o4[base + i] = make_float4(v, v, v, v);
        }
    }
}

extern "C" void kernel_launch(void* const* d_in, const int* in_sizes, int n_in,
                              void* d_out, int out_size) {
    const int*   dur   = (const int*)d_in[0];
    const float* token = (const float*)d_in[1];
    float* out = (float*)d_out;
    int T = in_sizes[0];
    if (T > T_MAX) T = T_MAX;
    int L = out_size / 128;

    prep_kernel<<<1, 1024>>>(dur, token, T);
    int nblk = (L + BL - 1) / BL;
    fill_kernel<<<nblk, 256>>>(out, L);
}

// round 2
// speedup vs baseline: 1.9096x; 1.9096x over previous
#include <cuda_runtime.h>

#define T_MAX 2048

__device__ float d_w[T_MAX];
__device__ float d_startf[T_MAX];
__device__ float d_endf[T_MAX];
__device__ int   d_start_i[T_MAX];
__device__ int   d_dur_i[T_MAX];

__device__ __forceinline__ float reluf(float x) { return x > 0.f ? x : 0.f; }

__device__ __forceinline__ float rerelu_f(float x) {
    const float offs[24] = {3.25f,3.75f,5.25f,5.75f,6.25f,6.75f,11.25f,11.75f,
                            15.25f,15.75f,20.25f,20.75f,23.25f,23.75f,35.25f,35.75f,
                            40.25f,40.75f,43.25f,43.75f,49.25f,49.75f,61.25f,61.75f};
    const float cfs[24]  = {4.f,-4.f,-4.f,4.f,4.f,-4.f,-2.f,2.f,2.f,-2.f,-2.f,2.f,
                            2.f,-2.f,-2.f,2.f,2.f,-2.f,-2.f,2.f,2.f,-2.f,-2.f,2.f};
    float s = 0.f;
#pragma unroll
    for (int k = 0; k < 24; k++)
        s = __fadd_rn(s, __fmul_rn(cfs[k], reluf(__fadd_rn(x, -offs[k]))));
    return s;
}

__device__ __forceinline__ float rerelu2_f(float x) {
    const float offs[6] = {1.25f,1.75f,2.25f,2.75f,3.25f,3.75f};
    const float cfs[6]  = {-2.f,2.f,2.f,-2.f,-2.f,2.f};
    float s = 1.f;
#pragma unroll
    for (int k = 0; k < 6; k++)
        s = __fadd_rn(s, __fmul_rn(cfs[k], reluf(__fadd_rn(x, -offs[k]))));
    return s;
}

__device__ __forceinline__ float rerelu3_f(float x) {
    float s = __fmul_rn(2.f, reluf(__fadd_rn(x, -1.25f)));
    s = __fadd_rn(s, __fmul_rn(-2.f, reluf(__fadd_rn(x, -1.75f))));
    return s;
}

__device__ __forceinline__ float rerelu4_f(float x) {
    float s = __fmul_rn(8.f, reluf(x));
    s = __fadd_rn(s, __fmul_rn(-8.f,  reluf(__fadd_rn(x, -1.f))));
    s = __fadd_rn(s, __fmul_rn(-0.3f, reluf(__fadd_rn(x, -1.f))));
    s = __fadd_rn(s, __fmul_rn(0.3f,  reluf(__fadd_rn(x, -21.f))));
    return s;
}

// ---------------------------------------------------------------------------
// Kernel A (1 CTA): token prep. tok = rerelu(token); duration scan -> start_t;
// end_t = start_t + rerelu2(tok_t + tok_{t+1}) * dur_{t+1} + dur_t;
// w_t = rerelu3(tok_t)^2. NO owner scatter (that was the R1 bottleneck).
// ---------------------------------------------------------------------------
__global__ __launch_bounds__(1024) void prep_kernel(const int* __restrict__ dur,
                                                    const float* __restrict__ token,
                                                    int T) {
    __shared__ float s_tok[T_MAX + 1];
    __shared__ int   s_wsum[32];
    int tid = threadIdx.x;

    for (int t = tid; t <= T_MAX; t += 1024)
        s_tok[t] = (t < T) ? rerelu_f(token[t]) : 0.f;

    int t0 = 2 * tid, t1 = 2 * tid + 1;
    int d0 = (t0 < T) ? dur[t0] : 0;
    int d1 = (t1 < T) ? dur[t1] : 0;
    int d2 = (t1 + 1 < T) ? dur[t1 + 1] : 0;
    int pair = d0 + d1;

    int lane = tid & 31, wid = tid >> 5;
    int incl = pair;
#pragma unroll
    for (int o = 1; o < 32; o <<= 1) {
        int n = __shfl_up_sync(0xffffffffu, incl, o);
        if (lane >= o) incl += n;
    }
    if (lane == 31) s_wsum[wid] = incl;
    __syncthreads();
    if (wid == 0) {
        int v = s_wsum[lane];
        int wincl = v;
#pragma unroll
        for (int o = 1; o < 32; o <<= 1) {
            int n = __shfl_up_sync(0xffffffffu, wincl, o);
            if (lane >= o) wincl += n;
        }
        s_wsum[lane] = wincl - v;  // exclusive warp offset
    }
    __syncthreads();
    int excl = s_wsum[wid] + incl - pair;  // exclusive prefix before token t0

    int starts[2] = {excl, excl + d0};
    int ds[2] = {d0, d1};
    int dn[2] = {d1, d2};

#pragma unroll
    for (int j = 0; j < 2; j++) {
        int t = 2 * tid + j;
        if (t < T) {
            float st = s_tok[t];
            float x  = __fadd_rn(st, s_tok[t + 1]);
            float s2 = rerelu2_f(x);
            float nd = __fadd_rn(__fmul_rn(s2, (float)dn[j]), (float)ds[j]);
            float sf = (float)starts[j];
            d_startf[t]  = sf;
            d_endf[t]    = __fadd_rn(sf, nd);
            d_start_i[t] = starts[j];
            d_dur_i[t]   = ds[j];
            float nt = rerelu3_f(st);
            d_w[t] = __fmul_rn(nt, nt);
        }
    }
}

// ---------------------------------------------------------------------------
// Kernel B (grid = T): block b handles token b's frames [start, start+dur).
// Warp w handles frames k = w, w+4, ...; lanes compute S redundantly (same fp
// order as R1), each lane stores one float4 -> 512B coalesced per warp/frame.
// ---------------------------------------------------------------------------
__global__ __launch_bounds__(128) void fill_kernel(float* __restrict__ out, int T) {
    int t = blockIdx.x;
    int dcount = d_dur_i[t];
    if (dcount == 0) return;

    int start = d_start_i[t];
    float w  = d_w[t];
    float sf = d_startf[t];
    float wp = 0.f, sp = 0.f, ep = -1.f;
    if (t > 0) { wp = d_w[t - 1]; sp = d_startf[t - 1]; ep = d_endf[t - 1]; }

    int warp = threadIdx.x >> 5;
    int lane = threadIdx.x & 31;
    float4* o4 = (float4*)out;

    for (int k = warp; k < dcount; k += 4) {
        float lf = (float)(start + k);
        float S = __fmul_rn(w, __fadd_rn(__fadd_rn(lf, -sf), 1.f));
        if (lf < ep) {
            float c = __fmul_rn(wp, __fadd_rn(__fadd_rn(lf, -sp), 1.f));
            S = __fadd_rn(S, c);
        }
        float v = rerelu4_f(S);
        o4[(long long)(start + k) * 32 + lane] = make_float4(v, v, v, v);
    }
}

extern "C" void kernel_launch(void* const* d_in, const int* in_sizes, int n_in,
                              void* d_out, int out_size) {
    const int*   dur   = (const int*)d_in[0];
    const float* token = (const float*)d_in[1];
    float* out = (float*)d_out;
    int T = in_sizes[0];
    if (T > T_MAX) T = T_MAX;

    prep_kernel<<<1, 1024>>>(dur, token, T);
    fill_kernel<<<T, 128>>>(out, T);
}

// round 5
// speedup vs baseline: 2.3393x; 1.2250x over previous
#include <cuda_runtime.h>

#define TPC 8  // tokens per CTA; grid = ceil(T/8), must be <= blockDim (256)

__device__ __forceinline__ float reluf(float x) { return x > 0.f ? x : 0.f; }

__device__ __forceinline__ float rerelu_f(float x) {
    const float offs[24] = {3.25f,3.75f,5.25f,5.75f,6.25f,6.75f,11.25f,11.75f,
                            15.25f,15.75f,20.25f,20.75f,23.25f,23.75f,35.25f,35.75f,
                            40.25f,40.75f,43.25f,43.75f,49.25f,49.75f,61.25f,61.75f};
    const float cfs[24]  = {4.f,-4.f,-4.f,4.f,4.f,-4.f,-2.f,2.f,2.f,-2.f,-2.f,2.f,
                            2.f,-2.f,-2.f,2.f,2.f,-2.f,-2.f,2.f,2.f,-2.f,-2.f,2.f};
    float s = 0.f;
#pragma unroll
    for (int k = 0; k < 24; k++)
        s = __fadd_rn(s, __fmul_rn(cfs[k], reluf(__fadd_rn(x, -offs[k]))));
    return s;
}

__device__ __forceinline__ float rerelu2_f(float x) {
    const float offs[6] = {1.25f,1.75f,2.25f,2.75f,3.25f,3.75f};
    const float cfs[6]  = {-2.f,2.f,2.f,-2.f,-2.f,2.f};
    float s = 1.f;
#pragma unroll
    for (int k = 0; k < 6; k++)
        s = __fadd_rn(s, __fmul_rn(cfs[k], reluf(__fadd_rn(x, -offs[k]))));
    return s;
}

__device__ __forceinline__ float rerelu3_f(float x) {
    float s = __fmul_rn(2.f, reluf(__fadd_rn(x, -1.25f)));
    s = __fadd_rn(s, __fmul_rn(-2.f, reluf(__fadd_rn(x, -1.75f))));
    return s;
}

__device__ __forceinline__ float rerelu4_f(float x) {
    float s = __fmul_rn(8.f, reluf(x));
    s = __fadd_rn(s, __fmul_rn(-8.f,  reluf(__fadd_rn(x, -1.f))));
    s = __fadd_rn(s, __fmul_rn(-0.3f, reluf(__fadd_rn(x, -1.f))));
    s = __fadd_rn(s, __fmul_rn(0.3f,  reluf(__fadd_rn(x, -21.f))));
    return s;
}

// ---------------------------------------------------------------------------
// Single fused kernel. CTA c owns tokens [8c, 8c+8).
//  Phase 1: every CTA redundantly block-scans ALL durations (cheap, L2-hot).
//  Phase 2: 10 threads compute rerelu params for tokens 8c-1 .. 8c+8.
//  Phase 3: 8 warps fill the CTA's frames; one STG.128 per warp per frame.
// All fp op orders identical to the R2 kernel -> bit-identical output.
// ---------------------------------------------------------------------------
__global__ __launch_bounds__(256) void fused_kernel(const int* __restrict__ dur,
                                                    const float* __restrict__ token,
                                                    float* __restrict__ out, int T) {
    __shared__ int   s_wsum[8];
    __shared__ int   s_si[TPC + 1];   // starts for tokens 8c-1+r, r=0..8
    __shared__ int   s_di[TPC + 1];   // durations
    __shared__ float s_tok[TPC + 2];  // rerelu(token) for tokens 8c-1 .. 8c+8
    __shared__ float s_w[TPC + 1];
    __shared__ float s_sf[TPC + 1];
    __shared__ float s_ef[TPC + 1];

    int tid = threadIdx.x;
    int lane = tid & 31, wid = tid >> 5;
    int c = blockIdx.x;

    // ---- Phase 1: global duration scan (redundant per CTA) ----
    int base = tid * TPC;
    int d[TPC], pre[TPC];
    int run = 0;
    if (base + TPC <= T) {
        const int4* dur4 = (const int4*)(dur + base);
        int4 a = dur4[0], b = dur4[1];
        d[0]=a.x; d[1]=a.y; d[2]=a.z; d[3]=a.w;
        d[4]=b.x; d[5]=b.y; d[6]=b.z; d[7]=b.w;
    } else {
#pragma unroll
        for (int k = 0; k < TPC; k++) d[k] = (base + k < T) ? dur[base + k] : 0;
    }
#pragma unroll
    for (int k = 0; k < TPC; k++) { run += d[k]; pre[k] = run; }

    int incl = run;
#pragma unroll
    for (int o = 1; o < 32; o <<= 1) {
        int n = __shfl_up_sync(0xffffffffu, incl, o);
        if (lane >= o) incl += n;
    }
    if (lane == 31) s_wsum[wid] = incl;
    __syncthreads();
    if (tid == 0) {
        int acc = 0;
#pragma unroll
        for (int i = 0; i < 8; i++) { int v = s_wsum[i]; s_wsum[i] = acc; acc += v; }
    }
    __syncthreads();
    int ebase = s_wsum[wid] + (incl - run);  // exclusive prefix before token base

    // publish the starts this CTA needs
    if (tid == c) {
#pragma unroll
        for (int k = 0; k < TPC; k++) s_si[1 + k] = ebase + pre[k] - d[k];
    }
    if (c > 0) {
        if (tid == c - 1) s_si[0] = ebase + pre[TPC - 1] - d[TPC - 1];
    } else {
        if (tid == 0) s_si[0] = 0;
    }

    // ---- Phase 2a: tok = rerelu(token) for the 10 relevant tokens ----
    if (tid < TPC + 2) {
        int t = TPC * c - 1 + tid;
        s_tok[tid] = (t >= 0 && t < T) ? rerelu_f(token[t]) : 0.f;
    }
    __syncthreads();

    // ---- Phase 2b: per-token params ----
    if (tid < TPC + 1) {
        int t = TPC * c - 1 + tid;
        int di = 0;
        if (t >= 0 && t < T) di = dur[t];
        int dn = (t + 1 < T && t + 1 >= 0) ? dur[t + 1] : 0;
        float x  = __fadd_rn(s_tok[tid], s_tok[tid + 1]);
        float s2 = rerelu2_f(x);
        float nd = __fadd_rn(__fmul_rn(s2, (float)dn), (float)di);
        float sf = (float)s_si[tid];
        s_sf[tid] = sf;
        s_ef[tid] = __fadd_rn(sf, nd);
        float nt = rerelu3_f(s_tok[tid]);
        s_w[tid]  = __fmul_rn(nt, nt);
        s_di[tid] = di;
    }
    __syncthreads();

    // ---- Phase 3: fill this CTA's frames ----
    int S0 = s_si[1];
    int F  = (s_si[TPC] + s_di[TPC]) - S0;

    float4* o4 = (float4*)out + (long long)S0 * 32 + lane;
    for (int j = wid; j < F; j += 8) {
        int l = S0 + j;
        // owner r in [1, TPC]: largest r with s_si[r] <= l (skips dur-0 tokens)
        int r = 1;
#pragma unroll
        for (int k = 2; k <= TPC; k++) r += (l >= s_si[k]) ? 1 : 0;
        float lf = (float)l;
        float S = __fmul_rn(s_w[r], __fadd_rn(__fadd_rn(lf, -s_sf[r]), 1.f));
        int t = TPC * c - 1 + r;
        if (t > 0) {
            if (lf < s_ef[r - 1]) {
                float cc = __fmul_rn(s_w[r - 1],
                                     __fadd_rn(__fadd_rn(lf, -s_sf[r - 1]), 1.f));
                S = __fadd_rn(S, cc);
            }
        }
        float v = rerelu4_f(S);
        o4[(long long)j * 32] = make_float4(v, v, v, v);
    }
}

extern "C" void kernel_launch(void* const* d_in, const int* in_sizes, int n_in,
                              void* d_out, int out_size) {
    const int*   dur   = (const int*)d_in[0];
    const float* token = (const float*)d_in[1];
    float* out = (float*)d_out;
    int T = in_sizes[0];
    if (T > 2048) T = 2048;  // scan layout supports up to 256 threads * 8

    int nblk = (T + TPC - 1) / TPC;
    fused_kernel<<<nblk, 256>>>(dur, token, out, T);
}

// round 6
// speedup vs baseline: 2.3477x; 1.0036x over previous
#include <cuda_runtime.h>

#define TPC 2  // tokens per CTA

__device__ __forceinline__ float reluf(float x) { return x > 0.f ? x : 0.f; }

__device__ __forceinline__ float rerelu_f(float x) {
    const float offs[24] = {3.25f,3.75f,5.25f,5.75f,6.25f,6.75f,11.25f,11.75f,
                            15.25f,15.75f,20.25f,20.75f,23.25f,23.75f,35.25f,35.75f,
                            40.25f,40.75f,43.25f,43.75f,49.25f,49.75f,61.25f,61.75f};
    const float cfs[24]  = {4.f,-4.f,-4.f,4.f,4.f,-4.f,-2.f,2.f,2.f,-2.f,-2.f,2.f,
                            2.f,-2.f,-2.f,2.f,2.f,-2.f,-2.f,2.f,2.f,-2.f,-2.f,2.f};
    float s = 0.f;
#pragma unroll
    for (int k = 0; k < 24; k++)
        s = __fadd_rn(s, __fmul_rn(cfs[k], reluf(__fadd_rn(x, -offs[k]))));
    return s;
}

__device__ __forceinline__ float rerelu2_f(float x) {
    const float offs[6] = {1.25f,1.75f,2.25f,2.75f,3.25f,3.75f};
    const float cfs[6]  = {-2.f,2.f,2.f,-2.f,-2.f,2.f};
    float s = 1.f;
#pragma unroll
    for (int k = 0; k < 6; k++)
        s = __fadd_rn(s, __fmul_rn(cfs[k], reluf(__fadd_rn(x, -offs[k]))));
    return s;
}

__device__ __forceinline__ float rerelu3_f(float x) {
    float s = __fmul_rn(2.f, reluf(__fadd_rn(x, -1.25f)));
    s = __fadd_rn(s, __fmul_rn(-2.f, reluf(__fadd_rn(x, -1.75f))));
    return s;
}

__device__ __forceinline__ float rerelu4_f(float x) {
    float s = __fmul_rn(8.f, reluf(x));
    s = __fadd_rn(s, __fmul_rn(-8.f,  reluf(__fadd_rn(x, -1.f))));
    s = __fadd_rn(s, __fmul_rn(-0.3f, reluf(__fadd_rn(x, -1.f))));
    s = __fadd_rn(s, __fmul_rn(0.3f,  reluf(__fadd_rn(x, -21.f))));
    return s;
}

// ---------------------------------------------------------------------------
// One kernel, grid = ceil(T/TPC) CTAs of 128 threads. Warp 0 does ALL prep:
//  - lane L scans durations of tokens [64L, 64L+64) (int4 loads, truncated
//    past this CTA's last needed token), capturing prefix/dur for the TPC+2
//    tokens this CTA touches via predicated smem writes;
//  - shuffle exclusive-scan of lane sums; params for tokens tfirst..tfirst+TPC.
//  Then ONE __syncthreads; 4 warps fill the CTA's frames, one 512B
//  coalesced STG.128 per warp per frame. fp order identical to R2/R5.
// ---------------------------------------------------------------------------
__global__ __launch_bounds__(128) void fused_kernel(const int* __restrict__ dur,
                                                    const float* __restrict__ token,
                                                    float* __restrict__ out, int T) {
    __shared__ int   s_pre[TPC + 2];
    __shared__ int   s_dr[TPC + 2];
    __shared__ int   s_laneExcl[32];
    __shared__ int   s_si[TPC + 1];
    __shared__ int   s_di[TPC + 1];
    __shared__ float s_w[TPC + 1], s_sf[TPC + 1], s_ef[TPC + 1];

    int tid = threadIdx.x, lane = tid & 31, wid = tid >> 5;
    int c = blockIdx.x;
    int tfirst = TPC * c - 1;        // predecessor token index
    int needHi = TPC * c + TPC;      // last token index we need (for next-dur)

    if (wid == 0) {
        // Early: token loads + rerelu for tokens tfirst .. tfirst+TPC+1
        float tokv = 0.f;
        int tt = tfirst + lane;
        if (lane < TPC + 2 && tt >= 0 && tt < T)
            tokv = rerelu_f(token[tt]);
        float tok_next = __shfl_down_sync(0xffffffffu, tokv, 1);

        if (lane < TPC + 2) { s_pre[lane] = 0; s_dr[lane] = 0; }
        __syncwarp();

        const int4* dur4 = (const int4*)dur;
        int run = 0;
#pragma unroll
        for (int k = 0; k < 16; k++) {
            int g = (lane * 16 + k) * 4;  // first token of this int4 group
            int4 v = make_int4(0, 0, 0, 0);
            if (g <= needHi && g < T) v = dur4[lane * 16 + k];
            int p01 = v.x + v.y;
            int p012 = p01 + v.z;
            int r0 = g - tfirst;
            if (r0 >= 0     && r0 < TPC + 2)     { s_pre[r0]     = run;        s_dr[r0]     = v.x; }
            if (r0 + 1 >= 0 && r0 + 1 < TPC + 2) { s_pre[r0 + 1] = run + v.x;  s_dr[r0 + 1] = v.y; }
            if (r0 + 2 >= 0 && r0 + 2 < TPC + 2) { s_pre[r0 + 2] = run + p01;  s_dr[r0 + 2] = v.z; }
            if (r0 + 3 >= 0 && r0 + 3 < TPC + 2) { s_pre[r0 + 3] = run + p012; s_dr[r0 + 3] = v.w; }
            run += p012 + v.w;
        }
        // exclusive scan of lane sums
        int incl = run;
#pragma unroll
        for (int o = 1; o < 32; o <<= 1) {
            int n = __shfl_up_sync(0xffffffffu, incl, o);
            if (lane >= o) incl += n;
        }
        s_laneExcl[lane] = incl - run;
        __syncwarp();

        if (lane <= TPC) {
            int t = tfirst + lane;
            int start = 0, di = 0;
            if (t >= 0) {
                di = s_dr[lane];
                start = s_pre[lane] + s_laneExcl[t >> 6];
            }
            int dn = s_dr[lane + 1];
            float x  = __fadd_rn(tokv, tok_next);
            float s2 = rerelu2_f(x);
            float nd = __fadd_rn(__fmul_rn(s2, (float)dn), (float)di);
            float sf = (float)start;
            s_sf[lane] = sf;
            s_ef[lane] = __fadd_rn(sf, nd);
            float nt = rerelu3_f(tokv);
            s_w[lane]  = __fmul_rn(nt, nt);
            s_si[lane] = start;
            s_di[lane] = di;
        }
    }
    __syncthreads();

    // ---- fill this CTA's frames ----
    int S0 = s_si[1];
    int F  = (s_si[TPC] + s_di[TPC]) - S0;

    float4* o4 = (float4*)out + (long long)S0 * 32 + lane;
    for (int j = wid; j < F; j += 4) {
        int l = S0 + j;
        int r = 1;
#pragma unroll
        for (int k = 2; k <= TPC; k++) r += (l >= s_si[k]) ? 1 : 0;
        float lf = (float)l;
        float S = __fmul_rn(s_w[r], __fadd_rn(__fadd_rn(lf, -s_sf[r]), 1.f));
        if (tfirst + r > 0) {
            if (lf < s_ef[r - 1]) {
                float cc = __fmul_rn(s_w[r - 1],
                                     __fadd_rn(__fadd_rn(lf, -s_sf[r - 1]), 1.f));
                S = __fadd_rn(S, cc);
            }
        }
        float v = rerelu4_f(S);
        o4[(long long)j * 32] = make_float4(v, v, v, v);
    }
}

extern "C" void kernel_launch(void* const* d_in, const int* in_sizes, int n_in,
                              void* d_out, int out_size) {
    const int*   dur   = (const int*)d_in[0];
    const float* token = (const float*)d_in[1];
    float* out = (float*)d_out;
    int T = in_sizes[0];
    if (T > 2048) T = 2048;  // warp-0 scan covers up to 32 lanes * 64 tokens

    int nblk = (T + TPC - 1) / TPC;
    fused_kernel<<<nblk, 128>>>(dur, token, out, T);
}